// round 14
// baseline (speedup 1.0000x reference)
#include <cuda_runtime.h>
#include <cstddef>

typedef unsigned long long ull;

// ---------------- scratch (static device globals; no allocation) ----------------
__device__ float g_h64[4096 * 64];     // LSTM1 final hidden
__device__ float g_h256[4096 * 256];   // LSTM2 hidden

// ---------------- packed f32x2 helpers ----------------
__device__ __forceinline__ ull pk(float lo, float hi) {
    ull r;
    asm("mov.b64 %0, {%1, %2};" : "=l"(r) : "f"(lo), "f"(hi));
    return r;
}
__device__ __forceinline__ void fma2(ull& d, ull a, ull b) {
    asm("fma.rn.f32x2 %0, %1, %2, %0;" : "+l"(d) : "l"(a), "l"(b));
}
__device__ __forceinline__ float2 upk(ull v) {
    float2 r;
    asm("mov.b64 {%0, %1}, %2;" : "=f"(r.x), "=f"(r.y) : "l"(v));
    return r;
}

// accurate activations for LSTM2 path (expf ~2ulp)
__device__ __forceinline__ float sigf(float x) {
    return __fdividef(1.0f, 1.0f + __expf(-x));
}
__device__ __forceinline__ float tanh_(float x) {
    return __fdividef(2.0f, 1.0f + __expf(-2.0f * x)) - 1.0f;
}

// 7-MUFU LSTM cell (algebraically identical to sigmoid/tanh form)
__device__ __forceinline__ float lstm_cell(float i_, float f_, float g_, float o_,
                                           float& c) {
    float ef = __expf(-f_);
    float ei = __expf(-i_);
    float eg = __expf(-2.0f * g_);
    float p  = (1.0f + ei) * (1.0f + eg);
    float num = fmaf(c, p, (1.0f - eg) * (1.0f + ef));
    float den = (1.0f + ef) * p;
    c = __fdividef(num, den);
    float eo = __expf(-o_);
    float ec = __expf(-2.0f * c);
    return __fdividef(1.0f - ec, (1.0f + eo) * (1.0f + ec));
}

// ---------------- shared layout for LSTM1 (float offsets) ----------------
// Wq   float4[42][128]             : 21504 floats (k-pair packed weights)
// ACT  float4[4 warp][2 buf][42][5]: 8*210 float4 = 6720 floats, NON-duplicated
//      row kk, slot = parity*2 + q -> float4 a[2kk+parity][4q..4q+3]; slot 4 = pad
// bsh [256], eW [64]
#define S_WQ    0
#define S_ACT   21504
#define S_BSH   (S_ACT + 6720)       // 28224
#define S_EW    (S_BSH + 256)        // 28480
#define S_TOT   (S_EW + 64)          // 28544 floats = 114176 B
#define AKROW   5                     // float4 per kk row (4 slots + 1 pad)
#define ABUF    210                   // float4 per buffer (42 * 5)

__global__ void __launch_bounds__(128, 1)
lstm1_kernel(const float* __restrict__ x,
             const float* __restrict__ W_embed,
             const float* __restrict__ Wih1,
             const float* __restrict__ Whh1,
             const float* __restrict__ b1)
{
    extern __shared__ float sm[];
    float4* Wq4  = reinterpret_cast<float4*>(sm + S_WQ);
    float4* ACT4 = reinterpret_cast<float4*>(sm + S_ACT);
    float*  bsh  = sm + S_BSH;
    float*  eW   = sm + S_EW;

    const int tid = threadIdx.x;
    const int bt  = blockIdx.x;          // batch tile (32 elems)

    // combined paired-k weight (gate order i|f|g|o)
    for (int idx = tid; idx < 42 * 128; idx += 128) {
        int kk = idx >> 7, pj = idx & 127;
        int g0 = 2 * pj;
        int k0 = 2 * kk, k1 = k0 + 1;
        float4 v;
        v.x = (k0 < 20) ? __ldg(&Wih1[g0 * 20 + k0])     : __ldg(&Whh1[g0 * 64 + (k0 - 20)]);
        v.y = (k0 < 20) ? __ldg(&Wih1[(g0+1) * 20 + k0]) : __ldg(&Whh1[(g0+1) * 64 + (k0 - 20)]);
        v.z = (k1 < 20) ? __ldg(&Wih1[g0 * 20 + k1])     : __ldg(&Whh1[g0 * 64 + (k1 - 20)]);
        v.w = (k1 < 20) ? __ldg(&Wih1[(g0+1) * 20 + k1]) : __ldg(&Whh1[(g0+1) * 64 + (k1 - 20)]);
        Wq4[idx] = v;
    }
    for (int idx = tid; idx < 256; idx += 128) bsh[idx] = b1[idx];
    if (tid < 40) eW[tid] = W_embed[tid];
    // zero all act buffers
    for (int idx = tid; idx < 8 * ABUF; idx += 128)
        ACT4[idx] = make_float4(0.f, 0.f, 0.f, 0.f);
    __syncthreads();

    // ---- mapping: warp w owns batches w*8..w*8+7 end-to-end ----
    // lane l: gate pair j0 = 2l (covers all 64 j across the warp), all 8 batches
    const int w = tid >> 5, l = tid & 31;
    const int j0 = 2 * l;

    float4* actW0 = ACT4 + (w * 2) * ABUF;   // buffer parity 0
    float4* actW1 = actW0 + ABUF;            // buffer parity 1

    const float4* W4I = Wq4 + l;             // pj = l for type i
    const float4* W4F = W4I + 32;
    const float4* W4G = W4I + 64;
    const float4* W4O = W4I + 96;

    const ull bI = pk(bsh[j0],       bsh[j0 + 1]);
    const ull bF = pk(bsh[64 + j0],  bsh[64 + j0 + 1]);
    const ull bG = pk(bsh[128 + j0], bsh[128 + j0 + 1]);
    const ull bO = pk(bsh[192 + j0], bsh[192 + j0 + 1]);

    const int kkh = 10 + l;                  // h-row pair index for (j0, j0+1)

    // register-resident cell state: c[b] for j0 (cx) and j0+1 (cy)
    float cx[8], cy[8];
    #pragma unroll
    for (int b = 0; b < 8; b++) { cx[b] = 0.f; cy[b] = 0.f; }

    // embedding duty: lanes l<8 hold the token stream for batch l of this warp
    const float2* xrow = reinterpret_cast<const float2*>(x) +
                         (size_t)(bt * 32 + w * 8 + l) * 512;  // deref only l<8
    float2 tok = make_float2(0.f, 0.f), tok_nxt = make_float2(0.f, 0.f);
    if (l < 8) tok = xrow[0];
    // initial embedding (t=0) into warp buffer 0
    {
        float* a0f = reinterpret_cast<float*>(actW0);
        #pragma unroll
        for (int b = 0; b < 8; b++) {
            float tx = __shfl_sync(0xffffffffu, tok.x, b);
            float ty = __shfl_sync(0xffffffffu, tok.y, b);
            if (l < 20) {
                float v = fmaxf(fmaf(tx, eW[2 * l], ty * eW[2 * l + 1]), 0.0f);
                a0f[(l >> 1) * (AKROW * 4) + (l & 1) * 8 + (b >> 2) * 4 + (b & 3)] = v;
            }
        }
    }
    if (l < 8) tok_nxt = xrow[1];
    __syncthreads();

#define LOADP(wi,wf,wg,wo,aP0,aP1,aQ0,aQ1, kk) do {                               \
    wi = *reinterpret_cast<const ulonglong2*>(W4I + (kk) * 128);                  \
    wf = *reinterpret_cast<const ulonglong2*>(W4F + (kk) * 128);                  \
    wg = *reinterpret_cast<const ulonglong2*>(W4G + (kk) * 128);                  \
    wo = *reinterpret_cast<const ulonglong2*>(W4O + (kk) * 128);                  \
    aP0 = A4[(kk) * AKROW];         /* a[2kk][b0..b3]   */                        \
    aP1 = A4[(kk) * AKROW + 1];     /* a[2kk][b4..b7]   */                        \
    aQ0 = A4[(kk) * AKROW + 2];     /* a[2kk+1][b0..b3] */                        \
    aQ1 = A4[(kk) * AKROW + 3];     /* a[2kk+1][b4..b7] */                        \
} while (0)

#define COMPP(wi,wf,wg,wo,aP0,aP1,aQ0,aQ1) do {                                   \
    ull d[8];                                                                     \
    d[0]=pk(aP0.x,aP0.x); d[1]=pk(aP0.y,aP0.y);                                   \
    d[2]=pk(aP0.z,aP0.z); d[3]=pk(aP0.w,aP0.w);                                   \
    d[4]=pk(aP1.x,aP1.x); d[5]=pk(aP1.y,aP1.y);                                   \
    d[6]=pk(aP1.z,aP1.z); d[7]=pk(aP1.w,aP1.w);                                   \
    _Pragma("unroll")                                                             \
    for (int b = 0; b < 8; b++) {                                                 \
        fma2(accI[b], wi.x, d[b]); fma2(accF[b], wf.x, d[b]);                     \
        fma2(accG[b], wg.x, d[b]); fma2(accO[b], wo.x, d[b]);                     \
    }                                                                             \
    d[0]=pk(aQ0.x,aQ0.x); d[1]=pk(aQ0.y,aQ0.y);                                   \
    d[2]=pk(aQ0.z,aQ0.z); d[3]=pk(aQ0.w,aQ0.w);                                   \
    d[4]=pk(aQ1.x,aQ1.x); d[5]=pk(aQ1.y,aQ1.y);                                   \
    d[6]=pk(aQ1.z,aQ1.z); d[7]=pk(aQ1.w,aQ1.w);                                   \
    _Pragma("unroll")                                                             \
    for (int b = 0; b < 8; b++) {                                                 \
        fma2(accI[b], wi.y, d[b]); fma2(accF[b], wf.y, d[b]);                     \
        fma2(accG[b], wg.y, d[b]); fma2(accO[b], wo.y, d[b]);                     \
    }                                                                             \
} while (0)

    for (int t = 0; t < 512; t++) {
        float4* cur4 = (t & 1) ? actW1 : actW0;
        float4* nxt4 = (t & 1) ? actW0 : actW1;
        const float4* A4 = cur4;

        ull accI[8], accF[8], accG[8], accO[8];
        #pragma unroll
        for (int b = 0; b < 8; b++) { accI[b]=bI; accF[b]=bF; accG[b]=bG; accO[b]=bO; }

        // software-pipelined k-pair loop (42 pairs)
        ulonglong2 wiA,wfA,wgA,woA; float4 aP0A,aP1A,aQ0A,aQ1A;
        ulonglong2 wiB,wfB,wgB,woB; float4 aP0B,aP1B,aQ0B,aQ1B;
        LOADP(wiA,wfA,wgA,woA,aP0A,aP1A,aQ0A,aQ1A, 0);
        #pragma unroll 2
        for (int kk = 0; kk < 40; kk += 2) {
            LOADP(wiB,wfB,wgB,woB,aP0B,aP1B,aQ0B,aQ1B, kk + 1);
            COMPP(wiA,wfA,wgA,woA,aP0A,aP1A,aQ0A,aQ1A);
            LOADP(wiA,wfA,wgA,woA,aP0A,aP1A,aQ0A,aQ1A, kk + 2);
            COMPP(wiB,wfB,wgB,woB,aP0B,aP1B,aQ0B,aQ1B);
        }
        LOADP(wiB,wfB,wgB,woB,aP0B,aP1B,aQ0B,aQ1B, 41);
        COMPP(wiA,wfA,wgA,woA,aP0A,aP1A,aQ0A,aQ1A);
        COMPP(wiB,wfB,wgB,woB,aP0B,aP1B,aQ0B,aQ1B);

        // fused pointwise (7-MUFU cell; cell state in registers)
        float hx[8], hy[8];
        #pragma unroll
        for (int b = 0; b < 8; b++) {
            float2 vi = upk(accI[b]);
            float2 vf = upk(accF[b]);
            float2 vg = upk(accG[b]);
            float2 vo = upk(accO[b]);
            hx[b] = lstm_cell(vi.x, vf.x, vg.x, vo.x, cx[b]);
            hy[b] = lstm_cell(vi.y, vf.y, vg.y, vo.y, cy[b]);
        }

        // h stores: 4 STS.128 to warp-private next buffer, row kkh
        {
            float4* N4 = nxt4 + kkh * AKROW;
            N4[0] = make_float4(hx[0], hx[1], hx[2], hx[3]);
            N4[1] = make_float4(hx[4], hx[5], hx[6], hx[7]);
            N4[2] = make_float4(hy[0], hy[1], hy[2], hy[3]);
            N4[3] = make_float4(hy[4], hy[5], hy[6], hy[7]);
        }

        // embedding for t+1 (tokens prefetched a full step ahead)
        if (t < 511) {
            float* nxtf = reinterpret_cast<float*>(nxt4);
            #pragma unroll
            for (int b = 0; b < 8; b++) {
                float tx = __shfl_sync(0xffffffffu, tok_nxt.x, b);
                float ty = __shfl_sync(0xffffffffu, tok_nxt.y, b);
                if (l < 20) {
                    float v = fmaxf(fmaf(tx, eW[2 * l], ty * eW[2 * l + 1]), 0.0f);
                    nxtf[(l >> 1) * (AKROW * 4) + (l & 1) * 8 + (b >> 2) * 4 + (b & 3)] = v;
                }
            }
            if (l < 8 && t < 510) tok_nxt = xrow[t + 2];
        }
        __syncwarp();   // warp-private state: no block/group barrier needed
    }

    // final h (after step 512) lives in buffer 0 (t=511 odd -> nxt = actW0)
    {
        const float* a0f = reinterpret_cast<const float*>(actW0);
        for (int idx = l; idx < 512; idx += 32) {
            int bb = idx >> 6, j = idx & 63;
            g_h64[(size_t)(bt * 32 + w * 8 + bb) * 64 + j] =
                a0f[((20 + j) >> 1) * (AKROW * 4) + ((20 + j) & 1) * 8 +
                    (bb >> 2) * 4 + (bb & 3)];
        }
    }
#undef LOADP
#undef COMPP
}

// ---------------- LSTM2: single step, zero state -> f gate & Whh2 unused ----------------
__global__ void __launch_bounds__(256, 1)
lstm2_kernel(const float* __restrict__ Wih2, const float* __restrict__ b2)
{
    extern __shared__ float sm[];
    float* Ws   = sm;            // [type][k][j], type 0:i 1:g 2:o
    float* hact = sm + 49152;    // [k][b]
    const int tid = threadIdx.x;
    const int bt  = blockIdx.x;

    for (int idx = tid; idx < 3 * 64 * 256; idx += 256) {
        int tt = idx >> 14;
        int r  = idx & 16383;
        int k  = r >> 8, j = r & 255;
        int o  = (tt == 0) ? 0 : (tt == 1) ? 512 : 768;  // i, g, o offsets
        Ws[idx] = __ldg(&Wih2[(size_t)(o + j) * 64 + k]);
    }
    for (int idx = tid; idx < 2048; idx += 256) {
        int bb = idx >> 6, k = idx & 63;
        hact[k * 32 + bb] = g_h64[(size_t)(bt * 32 + bb) * 64 + k];
    }
    __syncthreads();

    const int w = tid >> 5, l = tid & 31;
    for (int jc = 0; jc < 4; jc++) {
        int j = jc * 64 + 2 * l;
        ull bI = pk(__ldg(&b2[j]),       __ldg(&b2[j + 1]));
        ull bG = pk(__ldg(&b2[512 + j]), __ldg(&b2[512 + j + 1]));
        ull bO = pk(__ldg(&b2[768 + j]), __ldg(&b2[768 + j + 1]));
        ull aI[4], aG[4], aO[4];
        #pragma unroll
        for (int q = 0; q < 4; q++) { aI[q] = bI; aG[q] = bG; aO[q] = bO; }

        #pragma unroll 4
        for (int k = 0; k < 64; k++) {
            float4 a = *reinterpret_cast<const float4*>(hact + k * 32 + 4 * w);
            ull a0 = pk(a.x, a.x), a1 = pk(a.y, a.y);
            ull a2 = pk(a.z, a.z), a3 = pk(a.w, a.w);
            float2 wi = *reinterpret_cast<const float2*>(Ws + k * 256 + j);
            float2 wg = *reinterpret_cast<const float2*>(Ws + 16384 + k * 256 + j);
            float2 wo = *reinterpret_cast<const float2*>(Ws + 32768 + k * 256 + j);
            ull wpi = pk(wi.x, wi.y), wpg = pk(wg.x, wg.y), wpo = pk(wo.x, wo.y);
            fma2(aI[0], wpi, a0); fma2(aI[1], wpi, a1);
            fma2(aI[2], wpi, a2); fma2(aI[3], wpi, a3);
            fma2(aG[0], wpg, a0); fma2(aG[1], wpg, a1);
            fma2(aG[2], wpg, a2); fma2(aG[3], wpg, a3);
            fma2(aO[0], wpo, a0); fma2(aO[1], wpo, a1);
            fma2(aO[2], wpo, a2); fma2(aO[3], wpo, a3);
        }
        #pragma unroll
        for (int q = 0; q < 4; q++) {
            float2 vi = upk(aI[q]);
            float2 vg = upk(aG[q]);
            float2 vo = upk(aO[q]);
            float c0 = sigf(vi.x) * tanh_(vg.x);
            float h0 = sigf(vo.x) * tanh_(c0);
            float c1 = sigf(vi.y) * tanh_(vg.y);
            float h1 = sigf(vo.y) * tanh_(c1);
            int bb = bt * 32 + 4 * w + q;
            *reinterpret_cast<float2*>(&g_h256[(size_t)bb * 256 + j]) =
                make_float2(h0, h1);
        }
    }
}

// ---------------- output projection: out = h256 @ Wout^T + bout ----------------
__global__ void __launch_bounds__(256)
out_kernel(const float* __restrict__ Wout, const float* __restrict__ bout,
           float* __restrict__ out)
{
    int gw = (blockIdx.x * 256 + threadIdx.x) >> 5;   // one warp per batch elem
    int l  = threadIdx.x & 31;
    if (gw >= 4096) return;
    const float* hrow = g_h256 + (size_t)gw * 256;
    float p0 = 0.0f, p1 = 0.0f;
    #pragma unroll
    for (int m = 0; m < 8; m++) {
        int j = l + 32 * m;
        float h = hrow[j];
        p0 = fmaf(h, __ldg(&Wout[j]), p0);
        p1 = fmaf(h, __ldg(&Wout[256 + j]), p1);
    }
    #pragma unroll
    for (int s = 16; s > 0; s >>= 1) {
        p0 += __shfl_xor_sync(0xffffffffu, p0, s);
        p1 += __shfl_xor_sync(0xffffffffu, p1, s);
    }
    if (l == 0) {
        out[gw * 2]     = p0 + __ldg(&bout[0]);
        out[gw * 2 + 1] = p1 + __ldg(&bout[1]);
    }
}

// ---------------- launch ----------------
extern "C" void kernel_launch(void* const* d_in, const int* in_sizes, int n_in,
                              void* d_out, int out_size)
{
    const float *x = nullptr, *W_embed = nullptr, *Wih1 = nullptr, *Whh1 = nullptr,
                *b1 = nullptr, *Wih2 = nullptr, *b2 = nullptr,
                *Wout = nullptr, *bout = nullptr;
    for (int i = 0; i < n_in; i++) {
        const float* p = (const float*)d_in[i];
        switch (in_sizes[i]) {
            case 4194304: x = p; break;        // (4096, 1024)
            case 40:      W_embed = p; break;  // (20, 2)
            case 5120:    Wih1 = p; break;     // (256, 20)
            case 16384:   Whh1 = p; break;     // (256, 64)
            case 256:     b1 = p; break;       // (256,)
            case 65536:   Wih2 = p; break;     // (1024, 64)
            case 262144:  /* Whh2 unused */ break;
            case 1024:    b2 = p; break;       // (1024,)
            case 512:     Wout = p; break;     // (2, 256)
            case 2:       bout = p; break;     // (2,)
            default: break;
        }
    }
    float* out = (float*)d_out;

    const int SMEM1 = S_TOT * 4;              // 114176 B
    const int SMEM2 = (49152 + 2048) * 4;     // 204800 B
    cudaFuncSetAttribute(lstm1_kernel, cudaFuncAttributeMaxDynamicSharedMemorySize, SMEM1);
    cudaFuncSetAttribute(lstm2_kernel, cudaFuncAttributeMaxDynamicSharedMemorySize, SMEM2);

    lstm1_kernel<<<128, 128, SMEM1>>>(x, W_embed, Wih1, Whh1, b1);
    lstm2_kernel<<<128, 256, SMEM2>>>(Wih2, b2);
    out_kernel<<<512, 256>>>(Wout, bout, out);
    (void)out_size;
}

// round 15
// speedup vs baseline: 1.0575x; 1.0575x over previous
#include <cuda_runtime.h>
#include <cstddef>

typedef unsigned long long ull;

// ---------------- scratch (static device globals; no allocation) ----------------
__device__ float g_h64[4096 * 64];     // LSTM1 final hidden
__device__ float g_h256[4096 * 256];   // LSTM2 hidden

// ---------------- packed f32x2 helpers ----------------
__device__ __forceinline__ ull pk(float lo, float hi) {
    ull r;
    asm("mov.b64 %0, {%1, %2};" : "=l"(r) : "f"(lo), "f"(hi));
    return r;
}
__device__ __forceinline__ void fma2(ull& d, ull a, ull b) {
    asm("fma.rn.f32x2 %0, %1, %2, %0;" : "+l"(d) : "l"(a), "l"(b));
}
__device__ __forceinline__ float2 upk(ull v) {
    float2 r;
    asm("mov.b64 {%0, %1}, %2;" : "=f"(r.x), "=f"(r.y) : "l"(v));
    return r;
}

// accurate activations for LSTM2 path (expf ~2ulp)
__device__ __forceinline__ float sigf(float x) {
    return __fdividef(1.0f, 1.0f + __expf(-x));
}
__device__ __forceinline__ float tanh_(float x) {
    return __fdividef(2.0f, 1.0f + __expf(-2.0f * x)) - 1.0f;
}

// 7-MUFU LSTM cell (algebraically identical to sigmoid/tanh form)
__device__ __forceinline__ float lstm_cell(float i_, float f_, float g_, float o_,
                                           float& c) {
    float ef = __expf(-f_);
    float ei = __expf(-i_);
    float eg = __expf(-2.0f * g_);
    float p  = (1.0f + ei) * (1.0f + eg);
    float num = fmaf(c, p, (1.0f - eg) * (1.0f + ef));
    float den = (1.0f + ef) * p;
    c = __fdividef(num, den);
    float eo = __expf(-o_);
    float ec = __expf(-2.0f * c);
    return __fdividef(1.0f - ec, (1.0f + eo) * (1.0f + ec));
}

// ---------------- shared layout for LSTM1 (float offsets) ----------------
// Wq   float4[42][128]             : 21504 floats (k-pair packed weights)
// ACT  float4[8 warp][2 buf][42][3]: 16*126 float4 = 8064 floats, NON-duplicated
//      row kk: slot 0 = a[2kk][b0..b3], slot 1 = a[2kk+1][b0..b3], slot 2 = pad
// bsh [256], eW [64]
#define S_WQ    0
#define S_ACT   21504
#define S_BSH   (S_ACT + 8064)       // 29568
#define S_EW    (S_BSH + 256)        // 29824
#define S_TOT   (S_EW + 64)          // 29888 floats = 119552 B
#define AKROW   3                     // float4 per kk row (2 slots + 1 pad)
#define ABUF    126                   // float4 per buffer (42 * 3)

__global__ void __launch_bounds__(256, 1)
lstm1_kernel(const float* __restrict__ x,
             const float* __restrict__ W_embed,
             const float* __restrict__ Wih1,
             const float* __restrict__ Whh1,
             const float* __restrict__ b1)
{
    extern __shared__ float sm[];
    float4* Wq4  = reinterpret_cast<float4*>(sm + S_WQ);
    float4* ACT4 = reinterpret_cast<float4*>(sm + S_ACT);
    float*  bsh  = sm + S_BSH;
    float*  eW   = sm + S_EW;

    const int tid = threadIdx.x;
    const int bt  = blockIdx.x;          // batch tile (32 elems)

    // combined paired-k weight (gate order i|f|g|o)
    for (int idx = tid; idx < 42 * 128; idx += 256) {
        int kk = idx >> 7, pj = idx & 127;
        int g0 = 2 * pj;
        int k0 = 2 * kk, k1 = k0 + 1;
        float4 v;
        v.x = (k0 < 20) ? __ldg(&Wih1[g0 * 20 + k0])     : __ldg(&Whh1[g0 * 64 + (k0 - 20)]);
        v.y = (k0 < 20) ? __ldg(&Wih1[(g0+1) * 20 + k0]) : __ldg(&Whh1[(g0+1) * 64 + (k0 - 20)]);
        v.z = (k1 < 20) ? __ldg(&Wih1[g0 * 20 + k1])     : __ldg(&Whh1[g0 * 64 + (k1 - 20)]);
        v.w = (k1 < 20) ? __ldg(&Wih1[(g0+1) * 20 + k1]) : __ldg(&Whh1[(g0+1) * 64 + (k1 - 20)]);
        Wq4[idx] = v;
    }
    bsh[tid] = b1[tid];
    if (tid < 40) eW[tid] = W_embed[tid];
    // zero all act buffers
    for (int idx = tid; idx < 16 * ABUF; idx += 256)
        ACT4[idx] = make_float4(0.f, 0.f, 0.f, 0.f);
    __syncthreads();

    // ---- mapping: warp w owns batches w*4..w*4+3 end-to-end (all 64 j) ----
    // lane l: gate pair j0 = 2l, all 4 batches
    const int w = tid >> 5, l = tid & 31;
    const int j0 = 2 * l;

    float4* actW0 = ACT4 + (w * 2) * ABUF;   // buffer parity 0
    float4* actW1 = actW0 + ABUF;            // buffer parity 1

    const float4* W4I = Wq4 + l;             // pj = l for type i
    const float4* W4F = W4I + 32;
    const float4* W4G = W4I + 64;
    const float4* W4O = W4I + 96;

    const ull bI = pk(bsh[j0],       bsh[j0 + 1]);
    const ull bF = pk(bsh[64 + j0],  bsh[64 + j0 + 1]);
    const ull bG = pk(bsh[128 + j0], bsh[128 + j0 + 1]);
    const ull bO = pk(bsh[192 + j0], bsh[192 + j0 + 1]);

    const int kkh = 10 + l;                  // h-row pair index for (j0, j0+1)

    // register-resident cell state: c[b] for j0 (cx) and j0+1 (cy)
    float cx[4], cy[4];
    #pragma unroll
    for (int b = 0; b < 4; b++) { cx[b] = 0.f; cy[b] = 0.f; }

    // embedding duty: lanes l<4 hold the token stream for batch l of this warp
    const float2* xrow = reinterpret_cast<const float2*>(x) +
                         (size_t)(bt * 32 + w * 4 + l) * 512;  // deref only l<4
    float2 tok = make_float2(0.f, 0.f), tok_nxt = make_float2(0.f, 0.f);
    if (l < 4) tok = xrow[0];
    // initial embedding (t=0) into warp buffer 0
    {
        float* a0f = reinterpret_cast<float*>(actW0);
        #pragma unroll
        for (int b = 0; b < 4; b++) {
            float tx = __shfl_sync(0xffffffffu, tok.x, b);
            float ty = __shfl_sync(0xffffffffu, tok.y, b);
            if (l < 20) {
                float v = fmaxf(fmaf(tx, eW[2 * l], ty * eW[2 * l + 1]), 0.0f);
                a0f[(l >> 1) * (AKROW * 4) + (l & 1) * 4 + b] = v;
            }
        }
    }
    if (l < 4) tok_nxt = xrow[1];
    __syncthreads();

#define LOADP(wi,wf,wg,wo,aP,aQ, kk) do {                                         \
    wi = *reinterpret_cast<const ulonglong2*>(W4I + (kk) * 128);                  \
    wf = *reinterpret_cast<const ulonglong2*>(W4F + (kk) * 128);                  \
    wg = *reinterpret_cast<const ulonglong2*>(W4G + (kk) * 128);                  \
    wo = *reinterpret_cast<const ulonglong2*>(W4O + (kk) * 128);                  \
    aP = A4[(kk) * AKROW];          /* a[2kk][b0..b3]   */                        \
    aQ = A4[(kk) * AKROW + 1];      /* a[2kk+1][b0..b3] */                        \
} while (0)

#define COMPP(wi,wf,wg,wo,aP,aQ) do {                                             \
    ull d[4];                                                                     \
    d[0]=pk(aP.x,aP.x); d[1]=pk(aP.y,aP.y);                                       \
    d[2]=pk(aP.z,aP.z); d[3]=pk(aP.w,aP.w);                                       \
    _Pragma("unroll")                                                             \
    for (int b = 0; b < 4; b++) {                                                 \
        fma2(accI[b], wi.x, d[b]); fma2(accF[b], wf.x, d[b]);                     \
        fma2(accG[b], wg.x, d[b]); fma2(accO[b], wo.x, d[b]);                     \
    }                                                                             \
    d[0]=pk(aQ.x,aQ.x); d[1]=pk(aQ.y,aQ.y);                                       \
    d[2]=pk(aQ.z,aQ.z); d[3]=pk(aQ.w,aQ.w);                                       \
    _Pragma("unroll")                                                             \
    for (int b = 0; b < 4; b++) {                                                 \
        fma2(accI[b], wi.y, d[b]); fma2(accF[b], wf.y, d[b]);                     \
        fma2(accG[b], wg.y, d[b]); fma2(accO[b], wo.y, d[b]);                     \
    }                                                                             \
} while (0)

    for (int t = 0; t < 512; t++) {
        float4* cur4 = (t & 1) ? actW1 : actW0;
        float4* nxt4 = (t & 1) ? actW0 : actW1;
        const float4* A4 = cur4;

        ull accI[4], accF[4], accG[4], accO[4];
        #pragma unroll
        for (int b = 0; b < 4; b++) { accI[b]=bI; accF[b]=bF; accG[b]=bG; accO[b]=bO; }

        // software-pipelined k-pair loop (42 pairs)
        ulonglong2 wiA,wfA,wgA,woA; float4 aPA,aQA;
        ulonglong2 wiB,wfB,wgB,woB; float4 aPB,aQB;
        LOADP(wiA,wfA,wgA,woA,aPA,aQA, 0);
        #pragma unroll 4
        for (int kk = 0; kk < 40; kk += 2) {
            LOADP(wiB,wfB,wgB,woB,aPB,aQB, kk + 1);
            COMPP(wiA,wfA,wgA,woA,aPA,aQA);
            LOADP(wiA,wfA,wgA,woA,aPA,aQA, kk + 2);
            COMPP(wiB,wfB,wgB,woB,aPB,aQB);
        }
        LOADP(wiB,wfB,wgB,woB,aPB,aQB, 41);
        COMPP(wiA,wfA,wgA,woA,aPA,aQA);
        COMPP(wiB,wfB,wgB,woB,aPB,aQB);

        // fused pointwise (7-MUFU cell; cell state in registers)
        float hx[4], hy[4];
        #pragma unroll
        for (int b = 0; b < 4; b++) {
            float2 vi = upk(accI[b]);
            float2 vf = upk(accF[b]);
            float2 vg = upk(accG[b]);
            float2 vo = upk(accO[b]);
            hx[b] = lstm_cell(vi.x, vf.x, vg.x, vo.x, cx[b]);
            hy[b] = lstm_cell(vi.y, vf.y, vg.y, vo.y, cy[b]);
        }

        // h stores: 2 STS.128 to warp-private next buffer, row kkh
        // (stride 48B/lane -> octet banks {0,12,24,4,16,28,8,20}: conflict-free)
        {
            float4* N4 = nxt4 + kkh * AKROW;
            N4[0] = make_float4(hx[0], hx[1], hx[2], hx[3]);
            N4[1] = make_float4(hy[0], hy[1], hy[2], hy[3]);
        }

        // embedding for t+1 (tokens prefetched a full step ahead)
        if (t < 511) {
            float* nxtf = reinterpret_cast<float*>(nxt4);
            #pragma unroll
            for (int b = 0; b < 4; b++) {
                float tx = __shfl_sync(0xffffffffu, tok_nxt.x, b);
                float ty = __shfl_sync(0xffffffffu, tok_nxt.y, b);
                if (l < 20) {
                    float v = fmaxf(fmaf(tx, eW[2 * l], ty * eW[2 * l + 1]), 0.0f);
                    nxtf[(l >> 1) * (AKROW * 4) + (l & 1) * 4 + b] = v;
                }
            }
            if (l < 4 && t < 510) tok_nxt = xrow[t + 2];
        }
        __syncwarp();   // warp-private state: no block barrier ever
    }

    // final h (after step 512) lives in buffer 0 (t=511 odd -> nxt = actW0)
    {
        const float* a0f = reinterpret_cast<const float*>(actW0);
        for (int idx = l; idx < 256; idx += 32) {
            int bb = idx >> 6, j = idx & 63;
            g_h64[(size_t)(bt * 32 + w * 4 + bb) * 64 + j] =
                a0f[((20 + j) >> 1) * (AKROW * 4) + ((20 + j) & 1) * 4 + bb];
        }
    }
#undef LOADP
#undef COMPP
}

// ---------------- LSTM2: single step, zero state -> f gate & Whh2 unused ----------------
__global__ void __launch_bounds__(256, 1)
lstm2_kernel(const float* __restrict__ Wih2, const float* __restrict__ b2)
{
    extern __shared__ float sm[];
    float* Ws   = sm;            // [type][k][j], type 0:i 1:g 2:o
    float* hact = sm + 49152;    // [k][b]
    const int tid = threadIdx.x;
    const int bt  = blockIdx.x;

    for (int idx = tid; idx < 3 * 64 * 256; idx += 256) {
        int tt = idx >> 14;
        int r  = idx & 16383;
        int k  = r >> 8, j = r & 255;
        int o  = (tt == 0) ? 0 : (tt == 1) ? 512 : 768;  // i, g, o offsets
        Ws[idx] = __ldg(&Wih2[(size_t)(o + j) * 64 + k]);
    }
    for (int idx = tid; idx < 2048; idx += 256) {
        int bb = idx >> 6, k = idx & 63;
        hact[k * 32 + bb] = g_h64[(size_t)(bt * 32 + bb) * 64 + k];
    }
    __syncthreads();

    const int w = tid >> 5, l = tid & 31;
    for (int jc = 0; jc < 4; jc++) {
        int j = jc * 64 + 2 * l;
        ull bI = pk(__ldg(&b2[j]),       __ldg(&b2[j + 1]));
        ull bG = pk(__ldg(&b2[512 + j]), __ldg(&b2[512 + j + 1]));
        ull bO = pk(__ldg(&b2[768 + j]), __ldg(&b2[768 + j + 1]));
        ull aI[4], aG[4], aO[4];
        #pragma unroll
        for (int q = 0; q < 4; q++) { aI[q] = bI; aG[q] = bG; aO[q] = bO; }

        #pragma unroll 4
        for (int k = 0; k < 64; k++) {
            float4 a = *reinterpret_cast<const float4*>(hact + k * 32 + 4 * w);
            ull a0 = pk(a.x, a.x), a1 = pk(a.y, a.y);
            ull a2 = pk(a.z, a.z), a3 = pk(a.w, a.w);
            float2 wi = *reinterpret_cast<const float2*>(Ws + k * 256 + j);
            float2 wg = *reinterpret_cast<const float2*>(Ws + 16384 + k * 256 + j);
            float2 wo = *reinterpret_cast<const float2*>(Ws + 32768 + k * 256 + j);
            ull wpi = pk(wi.x, wi.y), wpg = pk(wg.x, wg.y), wpo = pk(wo.x, wo.y);
            fma2(aI[0], wpi, a0); fma2(aI[1], wpi, a1);
            fma2(aI[2], wpi, a2); fma2(aI[3], wpi, a3);
            fma2(aG[0], wpg, a0); fma2(aG[1], wpg, a1);
            fma2(aG[2], wpg, a2); fma2(aG[3], wpg, a3);
            fma2(aO[0], wpo, a0); fma2(aO[1], wpo, a1);
            fma2(aO[2], wpo, a2); fma2(aO[3], wpo, a3);
        }
        #pragma unroll
        for (int q = 0; q < 4; q++) {
            float2 vi = upk(aI[q]);
            float2 vg = upk(aG[q]);
            float2 vo = upk(aO[q]);
            float c0 = sigf(vi.x) * tanh_(vg.x);
            float h0 = sigf(vo.x) * tanh_(c0);
            float c1 = sigf(vi.y) * tanh_(vg.y);
            float h1 = sigf(vo.y) * tanh_(c1);
            int bb = bt * 32 + 4 * w + q;
            *reinterpret_cast<float2*>(&g_h256[(size_t)bb * 256 + j]) =
                make_float2(h0, h1);
        }
    }
}

// ---------------- output projection: out = h256 @ Wout^T + bout ----------------
__global__ void __launch_bounds__(256)
out_kernel(const float* __restrict__ Wout, const float* __restrict__ bout,
           float* __restrict__ out)
{
    int gw = (blockIdx.x * 256 + threadIdx.x) >> 5;   // one warp per batch elem
    int l  = threadIdx.x & 31;
    if (gw >= 4096) return;
    const float* hrow = g_h256 + (size_t)gw * 256;
    float p0 = 0.0f, p1 = 0.0f;
    #pragma unroll
    for (int m = 0; m < 8; m++) {
        int j = l + 32 * m;
        float h = hrow[j];
        p0 = fmaf(h, __ldg(&Wout[j]), p0);
        p1 = fmaf(h, __ldg(&Wout[256 + j]), p1);
    }
    #pragma unroll
    for (int s = 16; s > 0; s >>= 1) {
        p0 += __shfl_xor_sync(0xffffffffu, p0, s);
        p1 += __shfl_xor_sync(0xffffffffu, p1, s);
    }
    if (l == 0) {
        out[gw * 2]     = p0 + __ldg(&bout[0]);
        out[gw * 2 + 1] = p1 + __ldg(&bout[1]);
    }
}

// ---------------- launch ----------------
extern "C" void kernel_launch(void* const* d_in, const int* in_sizes, int n_in,
                              void* d_out, int out_size)
{
    const float *x = nullptr, *W_embed = nullptr, *Wih1 = nullptr, *Whh1 = nullptr,
                *b1 = nullptr, *Wih2 = nullptr, *b2 = nullptr,
                *Wout = nullptr, *bout = nullptr;
    for (int i = 0; i < n_in; i++) {
        const float* p = (const float*)d_in[i];
        switch (in_sizes[i]) {
            case 4194304: x = p; break;        // (4096, 1024)
            case 40:      W_embed = p; break;  // (20, 2)
            case 5120:    Wih1 = p; break;     // (256, 20)
            case 16384:   Whh1 = p; break;     // (256, 64)
            case 256:     b1 = p; break;       // (256,)
            case 65536:   Wih2 = p; break;     // (1024, 64)
            case 262144:  /* Whh2 unused */ break;
            case 1024:    b2 = p; break;       // (1024,)
            case 512:     Wout = p; break;     // (2, 256)
            case 2:       bout = p; break;     // (2,)
            default: break;
        }
    }
    float* out = (float*)d_out;

    const int SMEM1 = S_TOT * 4;              // 119552 B
    const int SMEM2 = (49152 + 2048) * 4;     // 204800 B
    cudaFuncSetAttribute(lstm1_kernel, cudaFuncAttributeMaxDynamicSharedMemorySize, SMEM1);
    cudaFuncSetAttribute(lstm2_kernel, cudaFuncAttributeMaxDynamicSharedMemorySize, SMEM2);

    lstm1_kernel<<<128, 256, SMEM1>>>(x, W_embed, Wih1, Whh1, b1);
    lstm2_kernel<<<128, 256, SMEM2>>>(Wih2, b2);
    out_kernel<<<512, 256>>>(Wout, bout, out);
    (void)out_size;
}